// round 16
// baseline (speedup 1.0000x reference)
#include <cuda_runtime.h>
#include <cuda_fp16.h>
#include <cstdint>
#include <cstddef>

#define GH 1024
#define GW 1024
#define GC 32
#define GHW (GH * GW)

// 64 MB transposed fp16 params: [HW, C], 64B per cell. Pure scratch:
// fully rewritten by the transpose every replay, discarded after the gather.
__device__ __half g_params_h[(size_t)GHW * GC];

__device__ __forceinline__ uint64_t evict_last_policy() {
    uint64_t p;
    asm("createpolicy.fractional.L2::evict_last.b64 %0, 1.0;" : "=l"(p));
    return p;
}

__device__ __forceinline__ uint64_t evict_first_policy() {
    uint64_t p;
    asm("createpolicy.fractional.L2::evict_first.b64 %0, 1.0;" : "=l"(p));
    return p;
}

__device__ __forceinline__ void st16_hint(uint4* ptr, uint4 v, uint64_t pol) {
    asm volatile("st.global.L2::cache_hint.v4.u32 [%0], {%1,%2,%3,%4}, %5;"
                 :: "l"(ptr), "r"(v.x), "r"(v.y), "r"(v.z), "r"(v.w), "l"(pol)
                 : "memory");
}

__device__ __forceinline__ uint4 ld16_evict_last(const uint4* ptr, uint64_t pol) {
    uint4 r;
    asm volatile("ld.global.nc.L2::cache_hint.v4.u32 {%0,%1,%2,%3}, [%4], %5;"
                 : "=r"(r.x), "=r"(r.y), "=r"(r.z), "=r"(r.w)
                 : "l"(ptr), "l"(pol));
    return r;
}

__device__ __forceinline__ float2 ld8_evict_first(const float2* ptr, uint64_t pol) {
    float2 r;
    asm volatile("ld.global.nc.L2::cache_hint.v2.f32 {%0,%1}, [%2], %3;"
                 : "=f"(r.x), "=f"(r.y) : "l"(ptr), "l"(pol));
    return r;
}

// ---------------------------------------------------------------------------
// Kernel 1: transpose + convert, no smem. One thread = one point.
// Params enter L2 with evict_last priority.
// ---------------------------------------------------------------------------
__global__ void transpose_kernel(const float* __restrict__ in) {
    const int p = blockIdx.x * blockDim.x + threadIdx.x;
    const uint64_t pol = evict_last_policy();

    float v[32];
#pragma unroll
    for (int c = 0; c < 32; c++) v[c] = __ldcs(in + (size_t)c * GHW + p);

    uint4* __restrict__ outv = (uint4*)(g_params_h + (size_t)p * GC);
#pragma unroll
    for (int q = 0; q < 4; q++) {
        union { __half2 h2[4]; uint4 u; } pack;
#pragma unroll
        for (int j = 0; j < 4; j++)
            pack.h2[j] = __floats2half2_rn(v[q * 8 + 2 * j], v[q * 8 + 2 * j + 1]);
        st16_hint(outv + q, pack.u, pol);
    }
}

// ---------------------------------------------------------------------------
// Kernel 2: bilinear gather (best-measured structure: 4 lanes/point,
// 4x LDG.128, 32 regs, 84% occupancy). Param loads evict_last; coord loads
// and output stores evict_first.
// ---------------------------------------------------------------------------
__global__ void __launch_bounds__(256)
gather_kernel(const float* __restrict__ coord,
              float* __restrict__ out,
              int n_points) {
    const int t   = blockIdx.x * blockDim.x + threadIdx.x;
    const int p   = t >> 2;
    const int sub = t & 3;          // 8 channels per lane
    if (p >= n_points) return;

    const uint64_t pol_last  = evict_last_policy();
    const uint64_t pol_first = evict_first_policy();

    const float2 xy = ld8_evict_first(((const float2*)coord) + p, pol_first);

    const float ix = (xy.x + 1.0f) * 0.5f * (float)(GW - 1);
    const float iy = (xy.y + 1.0f) * 0.5f * (float)(GH - 1);

    const float fx0 = floorf(ix);
    const float fy0 = floorf(iy);
    const float wx1 = ix - fx0;
    const float wy1 = iy - fy0;
    const float wx0 = 1.0f - wx1;
    const float wy0 = 1.0f - wy1;

    int x0 = (int)fx0; x0 = x0 < 0 ? 0 : (x0 > GW - 1 ? GW - 1 : x0);
    int y0 = (int)fy0; y0 = y0 < 0 ? 0 : (y0 > GH - 1 ? GH - 1 : y0);
    int x1 = x0 + 1;   x1 = x1 > GW - 1 ? GW - 1 : x1;
    int y1 = y0 + 1;   y1 = y1 > GH - 1 ? GH - 1 : y1;

    const float w_nw = wx0 * wy0;
    const float w_ne = wx1 * wy0;
    const float w_sw = wx0 * wy1;
    const float w_se = wx1 * wy1;

    const uint4* __restrict__ base = (const uint4*)g_params_h;
    const uint4 r_nw = ld16_evict_last(base + (((size_t)y0 << 10) + x0) * 4 + sub, pol_last);
    const uint4 r_ne = ld16_evict_last(base + (((size_t)y0 << 10) + x1) * 4 + sub, pol_last);
    const uint4 r_sw = ld16_evict_last(base + (((size_t)y1 << 10) + x0) * 4 + sub, pol_last);
    const uint4 r_se = ld16_evict_last(base + (((size_t)y1 << 10) + x1) * 4 + sub, pol_last);

    float o[8];
#pragma unroll
    for (int h = 0; h < 4; h++) {
        const unsigned ua = (&r_nw.x)[h];
        const unsigned ub = (&r_ne.x)[h];
        const unsigned uc = (&r_sw.x)[h];
        const unsigned ud = (&r_se.x)[h];
        const float2 a = __half22float2(*(const __half2*)&ua);
        const float2 b = __half22float2(*(const __half2*)&ub);
        const float2 c = __half22float2(*(const __half2*)&uc);
        const float2 d = __half22float2(*(const __half2*)&ud);
        o[2 * h + 0] = a.x * w_nw + b.x * w_ne + c.x * w_sw + d.x * w_se;
        o[2 * h + 1] = a.y * w_nw + b.y * w_ne + c.y * w_sw + d.y * w_se;
    }

    uint4* __restrict__ ov = (uint4*)(((float4*)out) + (size_t)p * 8 + 2 * sub);
    union { float4 f; uint4 u; } s0, s1;
    s0.f = make_float4(o[0], o[1], o[2], o[3]);
    s1.f = make_float4(o[4], o[5], o[6], o[7]);
    st16_hint(ov + 0, s0.u, pol_first);
    st16_hint(ov + 1, s1.u, pol_first);
}

// ---------------------------------------------------------------------------
// Kernel 3: discard the scratch's L2 lines WITHOUT writeback. g_params_h is
// fully rewritten next replay, so its dirty bytes never need to reach DRAM.
// 64MB / 128B = 524288 lines; each thread discards 4.
// ---------------------------------------------------------------------------
__global__ void discard_kernel() {
    const size_t t = blockIdx.x * blockDim.x + threadIdx.x;
    const char* base = (const char*)g_params_h + t * 512;
#pragma unroll
    for (int i = 0; i < 4; i++) {
        asm volatile("discard.global.L2 [%0], 128;" :: "l"(base + i * 128) : "memory");
    }
}

extern "C" void kernel_launch(void* const* d_in, const int* in_sizes, int n_in,
                              void* d_out, int out_size) {
    const float* coord;
    const float* params;
    int coord_elems;
    if (in_sizes[0] < in_sizes[1]) {
        coord = (const float*)d_in[0];
        params = (const float*)d_in[1];
        coord_elems = in_sizes[0];
    } else {
        coord = (const float*)d_in[1];
        params = (const float*)d_in[0];
        coord_elems = in_sizes[1];
    }
    const int n_points = coord_elems / 2;

    transpose_kernel<<<GHW / 256, 256>>>(params);

    const int total_threads = n_points * 4;
    const int block = 256;
    const int grid = (total_threads + block - 1) / block;
    gather_kernel<<<grid, block>>>(coord, (float*)d_out, n_points);

    // 64MB scratch = 131072 threads x 4 lines.
    discard_kernel<<<512, 256>>>();
}